// round 14
// baseline (speedup 1.0000x reference)
#include <cuda_runtime.h>
#include <cuda_bf16.h>
#include <math.h>

#define NB   64
#define NL   200
#define NQC  1024
#define ND   256
#define NH   512
#define NG   1536
#define NQO  1024
#define NBL  (NB*NL)

#define NGRP   4
#define GBAT   16
#define JBLK   16
#define NBLKG  32
#define NBLK   (NGRP*NBLKG)   // 128 persistent blocks
#define GRUT   384            // GRU block threads (12 warps, 3/SMSP)

// ---------------- scratch (device globals) ----------------
__device__ float g_wsum[NG * ND];
__device__ float g_WA[2 * NG];
__device__ float g_WAD[2 * NG];
__device__ float g_WQ[(NQC + 1) * NG];
__device__ float g_WQD[(NQC + 1) * NG];
__device__ float g_v[NQO * NH];
__device__ float g_c0[NQO];
__device__ float g_xg[NL * NB * NG];         // [t][b][g] incl b_ih
__device__ float g_hs[(NL + 1) * NB * NH];   // [t][b][j]
__device__ float g_preds[NBL];
__device__ float g_pid2[1];
__device__ int g_slot[NGRP][NBLKG];

__device__ __forceinline__ float block_reduce256(float v, float* red) {
    int tid = threadIdx.x;
    red[tid] = v;
    __syncthreads();
    for (int s = 128; s > 0; s >>= 1) {
        if (tid < s) red[tid] += red[tid + s];
        __syncthreads();
    }
    float r = red[0];
    __syncthreads();
    return r;
}

// packed f32x2 helpers
__device__ __forceinline__ unsigned long long pk2(float lo, float hi) {
    unsigned long long r;
    asm("mov.b64 %0, {%1, %2};" : "=l"(r) : "f"(lo), "f"(hi));
    return r;
}
__device__ __forceinline__ void ffma2(unsigned long long& d, unsigned long long a,
                                      unsigned long long b) {
    asm("fma.rn.f32x2 %0, %1, %2, %0;" : "+l"(d) : "l"(a), "l"(b));
}
__device__ __forceinline__ float upk_sum(unsigned long long v) {
    float lo, hi;
    asm("mov.b64 {%0, %1}, %2;" : "=f"(lo), "=f"(hi) : "l"(v));
    return lo + hi;
}

// release/acquire flag ops (fence folded in)
__device__ __forceinline__ void st_release(int* p, int v) {
    asm volatile("st.release.gpu.global.s32 [%0], %1;" :: "l"(p), "r"(v) : "memory");
}
__device__ __forceinline__ int ld_acquire(int* p) {
    int v;
    asm volatile("ld.acquire.gpu.global.s32 %0, [%1];" : "=r"(v) : "l"(p) : "memory");
    return v;
}

// ---------------- fused prep ----------------
__global__ __launch_bounds__(256) void k_prep_all(const float* __restrict__ w_ih,
                                                  const float* __restrict__ qa_emb,
                                                  const float* __restrict__ qa_emb_diff,
                                                  const float* __restrict__ matrix,
                                                  const float* __restrict__ fc_b,
                                                  const int* __restrict__ pid_data,
                                                  const float* __restrict__ diff_parm) {
    int bid = blockIdx.x, tid = threadIdx.x;
    __shared__ float red[256];
    if (bid < 1536) {
        int g = bid, d = tid;
        float wl = w_ih[g * 512 + d];
        float wr = w_ih[g * 512 + 256 + d];
        g_wsum[g * 256 + d] = wl + wr;
        float r0 = block_reduce256(wl * qa_emb[d], red);
        float r1 = block_reduce256(wl * qa_emb[256 + d], red);
        float r2 = block_reduce256(wl * qa_emb_diff[d], red);
        float r3 = block_reduce256(wl * qa_emb_diff[256 + d], red);
        if (d == 0) {
            g_WA[g] = r0;  g_WA[NG + g] = r1;
            g_WAD[g] = r2; g_WAD[NG + g] = r3;
        }
    } else if (bid < 2560) {
        int k = bid - 1536;
        float s = 0.f;
        for (int q = tid; q < 1024; q += 256) s += matrix[k * 1024 + q] * fc_b[q];
        s = block_reduce256(s, red);
        if (tid == 0) g_c0[k] = s;
    } else if (bid < 2688) {
        int idx = (bid - 2560) * 256 + tid;       // < 64*512
        g_hs[idx] = 0.f;
        if (idx < NGRP * NBLKG) ((int*)g_slot)[idx] = 0;
    } else {
        float s = 0.f;
        for (int i = tid; i < NBL; i += 256) {
            float d = diff_parm[pid_data[i]];
            s += d * d;
        }
        s = block_reduce256(s, red);
        if (tid == 0) g_pid2[0] = s;
    }
}

// ---------------- GEMM tiles ----------------
// NT: C[M,N] = A[M,K] @ B[N,K]^T
__device__ __forceinline__ void sgemm_tile_nt(int M, int N, int K,
                                              const float* __restrict__ A, int lda,
                                              const float* __restrict__ B, int ldb,
                                              float* __restrict__ C, int ldc,
                                              int bx, int by) {
    __shared__ float As[16][68];
    __shared__ float Bs[16][68];
    int n0 = bx * 64, m0 = by * 64;
    int tid = threadIdx.x;
    int tx = tid & 15, ty = tid >> 4;
    float acc[4][4] = {};
    int lm = tid >> 2;
    int lk = (tid & 3) * 4;
    for (int k0 = 0; k0 < K; k0 += 16) {
        float4 av = make_float4(0.f, 0.f, 0.f, 0.f);
        float4 bv = make_float4(0.f, 0.f, 0.f, 0.f);
        if (m0 + lm < M) av = *(const float4*)&A[(size_t)(m0 + lm) * lda + k0 + lk];
        if (n0 + lm < N) bv = *(const float4*)&B[(size_t)(n0 + lm) * ldb + k0 + lk];
        __syncthreads();
        As[lk + 0][lm] = av.x; As[lk + 1][lm] = av.y; As[lk + 2][lm] = av.z; As[lk + 3][lm] = av.w;
        Bs[lk + 0][lm] = bv.x; Bs[lk + 1][lm] = bv.y; Bs[lk + 2][lm] = bv.z; Bs[lk + 3][lm] = bv.w;
        __syncthreads();
#pragma unroll
        for (int k = 0; k < 16; k++) {
            float4 a = *(const float4*)&As[k][ty * 4];
            float4 b = *(const float4*)&Bs[k][tx * 4];
            acc[0][0] += a.x * b.x; acc[0][1] += a.x * b.y; acc[0][2] += a.x * b.z; acc[0][3] += a.x * b.w;
            acc[1][0] += a.y * b.x; acc[1][1] += a.y * b.y; acc[1][2] += a.y * b.z; acc[1][3] += a.y * b.w;
            acc[2][0] += a.z * b.x; acc[2][1] += a.z * b.y; acc[2][2] += a.z * b.z; acc[2][3] += a.z * b.w;
            acc[3][0] += a.w * b.x; acc[3][1] += a.w * b.y; acc[3][2] += a.w * b.z; acc[3][3] += a.w * b.w;
        }
    }
#pragma unroll
    for (int i = 0; i < 4; i++) {
        int m = m0 + ty * 4 + i;
        if (m < M) {
#pragma unroll
            for (int j = 0; j < 4; j++) {
                int n = n0 + tx * 4 + j;
                if (n < N) C[(size_t)m * ldc + n] = acc[i][j];
            }
        }
    }
}

// NN: C[M,N] = A[M,K] @ B[K,N]
__device__ __forceinline__ void sgemm_tile_nn(int M, int N, int K,
                                              const float* __restrict__ A, int lda,
                                              const float* __restrict__ B, int ldb,
                                              float* __restrict__ C, int ldc,
                                              int bx, int by) {
    __shared__ float As[16][68];
    __shared__ float Bs[16][68];
    int n0 = bx * 64, m0 = by * 64;
    int tid = threadIdx.x;
    int tx = tid & 15, ty = tid >> 4;
    float acc[4][4] = {};
    int lm = tid >> 2;
    int lk = (tid & 3) * 4;
    int bk = tid >> 4;
    int bn = (tid & 15) * 4;
    for (int k0 = 0; k0 < K; k0 += 16) {
        float4 av = make_float4(0.f, 0.f, 0.f, 0.f);
        if (m0 + lm < M) av = *(const float4*)&A[(size_t)(m0 + lm) * lda + k0 + lk];
        float4 bv = *(const float4*)&B[(size_t)(k0 + bk) * ldb + n0 + bn];
        __syncthreads();
        As[lk + 0][lm] = av.x; As[lk + 1][lm] = av.y; As[lk + 2][lm] = av.z; As[lk + 3][lm] = av.w;
        *(float4*)&Bs[bk][bn] = bv;
        __syncthreads();
#pragma unroll
        for (int k = 0; k < 16; k++) {
            float4 a = *(const float4*)&As[k][ty * 4];
            float4 b = *(const float4*)&Bs[k][tx * 4];
            acc[0][0] += a.x * b.x; acc[0][1] += a.x * b.y; acc[0][2] += a.x * b.z; acc[0][3] += a.x * b.w;
            acc[1][0] += a.y * b.x; acc[1][1] += a.y * b.y; acc[1][2] += a.y * b.z; acc[1][3] += a.y * b.w;
            acc[2][0] += a.z * b.x; acc[2][1] += a.z * b.y; acc[2][2] += a.z * b.z; acc[2][3] += a.z * b.w;
            acc[3][0] += a.w * b.x; acc[3][1] += a.w * b.y; acc[3][2] += a.w * b.z; acc[3][3] += a.w * b.w;
        }
    }
#pragma unroll
    for (int i = 0; i < 4; i++) {
        int m = m0 + ty * 4 + i;
        if (m < M) {
#pragma unroll
            for (int j = 0; j < 4; j++)
                C[(size_t)m * ldc + n0 + tx * 4 + j] = acc[i][j];
        }
    }
}

__global__ __launch_bounds__(256) void k_sgemm3(const float* __restrict__ q_emb,
                                                const float* __restrict__ q_emb_diff,
                                                const float* __restrict__ w_ih,
                                                const float* __restrict__ matrix,
                                                const float* __restrict__ fc_w) {
    int bid = blockIdx.x;
    if (bid < 408) {
        sgemm_tile_nt(NQC + 1, NG, ND, q_emb, ND, g_wsum, ND, g_WQ, NG,
                      bid % 24, bid / 24);
    } else if (bid < 816) {
        int lb = bid - 408;
        sgemm_tile_nt(NQC + 1, NG, ND, q_emb_diff, ND, w_ih + 256, 512, g_WQD, NG,
                      lb % 24, lb / 24);
    } else {
        int lb = bid - 816;
        sgemm_tile_nn(NQO, NH, NQO, matrix, NQO, fc_w, NH, g_v, NH,
                      lb % 8, lb / 8);
    }
}

// ---------------- xg assembly ----------------
__global__ __launch_bounds__(256) void k_xg(const int* __restrict__ q_data,
                                            const int* __restrict__ qa_data,
                                            const int* __restrict__ pid_data,
                                            const float* __restrict__ diff_parm,
                                            const float* __restrict__ b_ih) {
    int i = blockIdx.x;
    int b = i / NL, l = i % NL;
    int q = q_data[i];
    int a = (qa_data[i] - q) / NQC;
    float pid = diff_parm[pid_data[i]];
    const float* wq  = &g_WQ[(size_t)q * NG];
    const float* wqd = &g_WQD[(size_t)q * NG];
    const float* wa  = &g_WA[(size_t)a * NG];
    const float* wad = &g_WAD[(size_t)a * NG];
    float* dst = &g_xg[(size_t)(l * NB + b) * NG];
    for (int g = threadIdx.x; g < NG; g += 256)
        dst[g] = wq[g] + wa[g] + pid * (wqd[g] + wad[g]) + b_ih[g];
}

// ---------------- persistent GRU: 384 thr, 12 warps x 4 rows, SMEM h ------
__global__ __launch_bounds__(GRUT, 1) void k_gru_persist(const float* __restrict__ w_hh,
                                                         const float* __restrict__ b_hh) {
    __shared__ float s_hg[48 * 17];
    __shared__ float4 s_h[GBAT * 128];       // 16 batches x 512 floats = 32KB
    int tid  = threadIdx.x;
    int lane = tid & 31, wno = tid >> 5;     // wno 0..11
    int bx = blockIdx.x;
    int grp = bx & 3;
    int jblk = bx >> 2;
    int j0 = jblk * JBLK;
    int b0 = grp * GBAT;

    // each warp holds 4 w_hh rows in registers (packed pairs)
    unsigned long long wreg[4][8];
#pragma unroll
    for (int r4 = 0; r4 < 4; r4++) {
        int ridx = wno * 4 + r4;             // 0..47
        int gate = ridx >> 4, u = ridx & 15;
        int grow = gate * 512 + j0 + u;
#pragma unroll
        for (int r = 0; r < 4; r++) {
            float4 wv = *(const float4*)&w_hh[(size_t)grow * 512 + r * 128 + lane * 4];
            wreg[r4][2 * r]     = pk2(wv.x, wv.y);
            wreg[r4][2 * r + 1] = pk2(wv.z, wv.w);
        }
    }

    bool gactive = (tid < 256);
    int gu = tid & 15, gbl = (tid >> 4) & 15;
    int gb = b0 + gbl;
    float bi_r = 0.f, bi_z = 0.f, bi_n = 0.f;
    if (gactive) {
        bi_r = b_hh[j0 + gu];
        bi_z = b_hh[512 + j0 + gu];
        bi_n = b_hh[1024 + j0 + gu];
    }
    float hold = 0.0f;
    int half = lane >> 4;

    for (int t = 0; t < NL; t++) {
        // prefetch gate inputs for this step (linear addresses)
        float xr = 0.f, xz = 0.f, xn = 0.f;
        if (gactive) {
            const float* xg = &g_xg[((size_t)t * NB + gb) * NG];
            xr = xg[j0 + gu];
            xz = xg[512 + j0 + gu];
            xn = xg[1024 + j0 + gu];
        }

        // cooperative staged load: h[t] for 16 batches (contiguous 32KB), once
        {
            const float4* src = (const float4*)&g_hs[((size_t)t * NB + b0) * NH];
#pragma unroll
            for (int k = 0; k < 5; k++)
                s_h[tid + k * GRUT] = src[tid + k * GRUT];
            if (tid < 2048 - 5 * GRUT)
                s_h[tid + 5 * GRUT] = src[tid + 5 * GRUT];
        }
        __syncthreads();

#pragma unroll 2
        for (int bi = 0; bi < GBAT; bi++) {
            unsigned long long cur[8];
#pragma unroll
            for (int r = 0; r < 4; r++) {
                float4 hv = s_h[bi * 128 + r * 32 + lane];
                cur[2 * r]     = pk2(hv.x, hv.y);
                cur[2 * r + 1] = pk2(hv.z, hv.w);
            }
            float acc[4];
#pragma unroll
            for (int r4 = 0; r4 < 4; r4++) {
                unsigned long long a = 0ULL;
#pragma unroll
                for (int r = 0; r < 8; r++) ffma2(a, cur[r], wreg[r4][r]);
                acc[r4] = upk_sum(a);
            }
            // packed warp reduction: 4 values in 12 SHFL (same tree per value)
#pragma unroll
            for (int r4 = 0; r4 < 4; r4++)
                acc[r4] += __shfl_xor_sync(0xffffffffu, acc[r4], 16);
            float p0 = half ? acc[1] : acc[0];
            float p1 = half ? acc[3] : acc[2];
#pragma unroll
            for (int o = 8; o; o >>= 1) {
                p0 += __shfl_xor_sync(0xffffffffu, p0, o);
                p1 += __shfl_xor_sync(0xffffffffu, p1, o);
            }
            if ((lane & 15) == 0) {
                int rbase = wno * 4 + half;
                s_hg[(rbase + 0) * 17 + bi] = p0;
                s_hg[(rbase + 2) * 17 + bi] = p1;
            }
        }
        __syncthreads();
        // fused gates + h update (threads 0..255); s_hg row = gate*16+u
        if (gactive) {
            float hr = s_hg[gu * 17 + gbl] + bi_r;
            float hz = s_hg[(16 + gu) * 17 + gbl] + bi_z;
            float hn = s_hg[(32 + gu) * 17 + gbl] + bi_n;
            float r = 1.f / (1.f + expf(-(xr + hr)));
            float z = 1.f / (1.f + expf(-(xz + hz)));
            float n = tanhf(xn + r * hn);
            hold = (1.f - z) * n + z * hold;
            g_hs[((size_t)(t + 1) * NB + gb) * NH + j0 + gu] = hold;
        }
        __syncthreads();
        // one-hop barrier: release own slot, warp0 polls all 32 slots in parallel
        if (tid == 0) st_release(&g_slot[grp][jblk], t + 1);
        if (wno == 0) {
            unsigned done;
            do {
                int v = ld_acquire(&g_slot[grp][lane]);
                done = __ballot_sync(0xffffffffu, v >= t + 1);
            } while (done != 0xffffffffu);
        }
        __syncthreads();
    }
}

// ---------------- fused tail: mval + counts + dina (per batch) -------------
__global__ __launch_bounds__(256) void k_tail(const int* __restrict__ q_data,
                                              const int* __restrict__ qa_data) {
    __shared__ float s_m[NL], s_qa[NL], s_mc[NL], s_mi[NL], s_nmc[NL], s_aa[NL];
    __shared__ int s_q[NL];
    __shared__ float guess[NQO], slip[NQO];
    int b = blockIdx.x, tid = threadIdx.x;
    int lane = tid & 31, wid = tid >> 5;

    if (tid < NL) {
        int i = b * NL + tid;
        s_q[tid] = q_data[i];
        s_qa[tid] = (float)((qa_data[i] - q_data[i]) / NQC);
    }
    for (int j = tid; j < NQO; j += 256) { guess[j] = 0.f; slip[j] = 0.f; }
    __syncthreads();

    for (int l = wid; l < NL; l += 8) {
        int q = s_q[l] - 1;
        const float* h = &g_hs[(size_t)((l + 1) * NB + b) * NH];
        const float* vr = &g_v[(size_t)q * NH];
        float s = 0.f;
#pragma unroll
        for (int it = 0; it < 4; it++) {
            float4 hv = *(const float4*)&h[it * 128 + lane * 4];
            float4 vv = *(const float4*)&vr[it * 128 + lane * 4];
            s += hv.x * vv.x + hv.y * vv.y + hv.z * vv.z + hv.w * vv.w;
        }
#pragma unroll
        for (int o = 16; o; o >>= 1) s += __shfl_xor_sync(0xffffffffu, s, o);
        if (lane == 0) {
            float got = s + g_c0[q];
            s_m[l] = (got >= 0.4f) ? 1.0f : got;
        }
    }
    __syncthreads();

    if (tid < NL) {
        int qt = s_q[tid];
        float mc = 0.f, mi = 0.f, nmc = 0.f, aa = 1.f;
        for (int k = 0; k < tid; k++) {
            if (s_q[k] == qt) {
                aa += 1.f;
                float m = s_m[k];
                float mast = (m == 1.0f) ? 1.f : 0.f;
                float notm = (m == 0.0f) ? 1.f : 0.f;
                float a1 = s_qa[k], a0 = 1.f - a1;
                mc += a1 * mast; mi += a0 * mast; nmc += a0 * notm;
            }
        }
        s_mc[tid] = mc; s_mi[tid] = mi; s_nmc[tid] = nmc; s_aa[tid] = aa;
    }
    __syncthreads();

    if (tid == 0) {
        for (int t = 0; t < NL; t++) {
            int i = s_q[t] - 1;
            float m = s_m[t], qa = s_qa[t], aa = s_aa[t];
            float g_upd = (m == 1.0f) ? (s_mc[t] / aa)
                          : ((qa == 0.0f) ? (1.f - s_nmc[t] / aa) : (s_nmc[t] / aa));
            bool us = (m == 1.0f) && (qa == 0.0f);
            float ng = us ? guess[i] : g_upd;
            float ns = us ? (s_mi[t] / aa) : slip[i];
            guess[i] = ng; slip[i] = ns;
            float p = (1.f - ns) * (m * ng + (1.f - ns) * (1.f - m));
            g_preds[b * NL + t] = p;
        }
    }
}

// ---------------- final ----------------
__global__ __launch_bounds__(256) void k_final(const float* __restrict__ target,
                                               float* __restrict__ out) {
    int tid = threadIdx.x;
    float mse = 0.f, cnt = 0.f;
    for (int i = tid; i < NBL; i += 256) {
        float p = g_preds[i];
        float lab = target[i];
        float msk = (lab > -0.9f) ? 1.f : 0.f;
        float d = p - lab;
        mse += d * d * msk;
        cnt += msk;
        out[1 + i] = 1.f / (1.f + expf(-p));
    }
    __shared__ float red[256];
    mse = block_reduce256(mse, red);
    cnt = block_reduce256(cnt, red);
    if (tid == 0) {
        out[0] = mse + g_pid2[0] * 1e-5f;
        out[NBL + 1] = cnt;
    }
}

// ---------------- launch ----------------
extern "C" void kernel_launch(void* const* d_in, const int* in_sizes, int n_in,
                              void* d_out, int out_size) {
    const int*   q_data      = (const int*)d_in[0];
    const int*   qa_data     = (const int*)d_in[1];
    const int*   pid_data    = (const int*)d_in[2];
    const float* matrix      = (const float*)d_in[3];
    const float* target      = (const float*)d_in[4];
    const float* q_emb       = (const float*)d_in[5];
    const float* qa_emb      = (const float*)d_in[6];
    const float* q_emb_diff  = (const float*)d_in[7];
    const float* qa_emb_diff = (const float*)d_in[8];
    const float* diff_parm   = (const float*)d_in[9];
    const float* w_ih        = (const float*)d_in[10];
    const float* w_hh        = (const float*)d_in[11];
    const float* b_ih        = (const float*)d_in[12];
    const float* b_hh        = (const float*)d_in[13];
    const float* fc_w        = (const float*)d_in[14];
    const float* fc_b        = (const float*)d_in[15];
    float* out = (float*)d_out;

    k_prep_all<<<2689, 256>>>(w_ih, qa_emb, qa_emb_diff, matrix, fc_b,
                              pid_data, diff_parm);
    k_sgemm3<<<944, 256>>>(q_emb, q_emb_diff, w_ih, matrix, fc_w);
    k_xg<<<NBL, 256>>>(q_data, qa_data, pid_data, diff_parm, b_ih);
    k_gru_persist<<<NBLK, GRUT>>>(w_hh, b_hh);
    k_tail<<<NB, 256>>>(q_data, qa_data);
    k_final<<<1, 256>>>(target, out);
}

// round 15
// speedup vs baseline: 1.3817x; 1.3817x over previous
#include <cuda_runtime.h>
#include <cuda_bf16.h>
#include <math.h>

#define NB   64
#define NL   200
#define NQC  1024
#define ND   256
#define NH   512
#define NG   1536
#define NQO  1024
#define NBL  (NB*NL)

#define NGRP   4
#define GBAT   16
#define JBLK   16
#define NBLKG  32
#define NBLK   (NGRP*NBLKG)   // 128 persistent blocks
#define PST    68             // s_part row stride (16 batches * 4 partials + pad)

// ---------------- scratch (device globals) ----------------
__device__ float g_wsum[NG * ND];
__device__ float g_WA[2 * NG];
__device__ float g_WAD[2 * NG];
__device__ float g_WQ[(NQC + 1) * NG];
__device__ float g_WQD[(NQC + 1) * NG];
__device__ float g_v[NQO * NH];
__device__ float g_c0[NQO];
__device__ float g_xg[NL * NB * NG];         // [t][b][g] incl b_ih
__device__ float g_hs[(NL + 1) * NB * NH];   // [t][b][j]
__device__ float g_preds[NBL];
__device__ float g_pid2[1];
__device__ int g_slot[NGRP][NBLKG];
__device__ int g_barf[NGRP];

__device__ __forceinline__ float block_reduce256(float v, float* red) {
    int tid = threadIdx.x;
    red[tid] = v;
    __syncthreads();
    for (int s = 128; s > 0; s >>= 1) {
        if (tid < s) red[tid] += red[tid + s];
        __syncthreads();
    }
    float r = red[0];
    __syncthreads();
    return r;
}

// packed f32x2 helpers
__device__ __forceinline__ unsigned long long pk2(float lo, float hi) {
    unsigned long long r;
    asm("mov.b64 %0, {%1, %2};" : "=l"(r) : "f"(lo), "f"(hi));
    return r;
}
__device__ __forceinline__ void ffma2(unsigned long long& d, unsigned long long a,
                                      unsigned long long b) {
    asm("fma.rn.f32x2 %0, %1, %2, %0;" : "+l"(d) : "l"(a), "l"(b));
}
__device__ __forceinline__ float upk_sum(unsigned long long v) {
    float lo, hi;
    asm("mov.b64 {%0, %1}, %2;" : "=f"(lo), "=f"(hi) : "l"(v));
    return lo + hi;
}

// release/acquire flag ops (fence folded in)
__device__ __forceinline__ void st_release(int* p, int v) {
    asm volatile("st.release.gpu.global.s32 [%0], %1;" :: "l"(p), "r"(v) : "memory");
}
__device__ __forceinline__ int ld_acquire(int* p) {
    int v;
    asm volatile("ld.acquire.gpu.global.s32 %0, [%1];" : "=r"(v) : "l"(p) : "memory");
    return v;
}

// ---------------- fused prep ----------------
__global__ __launch_bounds__(256) void k_prep_all(const float* __restrict__ w_ih,
                                                  const float* __restrict__ qa_emb,
                                                  const float* __restrict__ qa_emb_diff,
                                                  const float* __restrict__ matrix,
                                                  const float* __restrict__ fc_b,
                                                  const int* __restrict__ pid_data,
                                                  const float* __restrict__ diff_parm) {
    int bid = blockIdx.x, tid = threadIdx.x;
    __shared__ float red[256];
    if (bid < 1536) {
        int g = bid, d = tid;
        float wl = w_ih[g * 512 + d];
        float wr = w_ih[g * 512 + 256 + d];
        g_wsum[g * 256 + d] = wl + wr;
        float r0 = block_reduce256(wl * qa_emb[d], red);
        float r1 = block_reduce256(wl * qa_emb[256 + d], red);
        float r2 = block_reduce256(wl * qa_emb_diff[d], red);
        float r3 = block_reduce256(wl * qa_emb_diff[256 + d], red);
        if (d == 0) {
            g_WA[g] = r0;  g_WA[NG + g] = r1;
            g_WAD[g] = r2; g_WAD[NG + g] = r3;
        }
    } else if (bid < 2560) {
        int k = bid - 1536;
        float s = 0.f;
        for (int q = tid; q < 1024; q += 256) s += matrix[k * 1024 + q] * fc_b[q];
        s = block_reduce256(s, red);
        if (tid == 0) g_c0[k] = s;
    } else if (bid < 2688) {
        int idx = (bid - 2560) * 256 + tid;       // < 64*512
        g_hs[idx] = 0.f;
        if (idx < NGRP) g_barf[idx] = 0;
        if (idx < NGRP * NBLKG) ((int*)g_slot)[idx] = 0;
    } else {
        float s = 0.f;
        for (int i = tid; i < NBL; i += 256) {
            float d = diff_parm[pid_data[i]];
            s += d * d;
        }
        s = block_reduce256(s, red);
        if (tid == 0) g_pid2[0] = s;
    }
}

// ---------------- GEMM tiles ----------------
// NT: C[M,N] = A[M,K] @ B[N,K]^T
__device__ __forceinline__ void sgemm_tile_nt(int M, int N, int K,
                                              const float* __restrict__ A, int lda,
                                              const float* __restrict__ B, int ldb,
                                              float* __restrict__ C, int ldc,
                                              int bx, int by) {
    __shared__ float As[16][68];
    __shared__ float Bs[16][68];
    int n0 = bx * 64, m0 = by * 64;
    int tid = threadIdx.x;
    int tx = tid & 15, ty = tid >> 4;
    float acc[4][4] = {};
    int lm = tid >> 2;
    int lk = (tid & 3) * 4;
    for (int k0 = 0; k0 < K; k0 += 16) {
        float4 av = make_float4(0.f, 0.f, 0.f, 0.f);
        float4 bv = make_float4(0.f, 0.f, 0.f, 0.f);
        if (m0 + lm < M) av = *(const float4*)&A[(size_t)(m0 + lm) * lda + k0 + lk];
        if (n0 + lm < N) bv = *(const float4*)&B[(size_t)(n0 + lm) * ldb + k0 + lk];
        __syncthreads();
        As[lk + 0][lm] = av.x; As[lk + 1][lm] = av.y; As[lk + 2][lm] = av.z; As[lk + 3][lm] = av.w;
        Bs[lk + 0][lm] = bv.x; Bs[lk + 1][lm] = bv.y; Bs[lk + 2][lm] = bv.z; Bs[lk + 3][lm] = bv.w;
        __syncthreads();
#pragma unroll
        for (int k = 0; k < 16; k++) {
            float4 a = *(const float4*)&As[k][ty * 4];
            float4 b = *(const float4*)&Bs[k][tx * 4];
            acc[0][0] += a.x * b.x; acc[0][1] += a.x * b.y; acc[0][2] += a.x * b.z; acc[0][3] += a.x * b.w;
            acc[1][0] += a.y * b.x; acc[1][1] += a.y * b.y; acc[1][2] += a.y * b.z; acc[1][3] += a.y * b.w;
            acc[2][0] += a.z * b.x; acc[2][1] += a.z * b.y; acc[2][2] += a.z * b.z; acc[2][3] += a.z * b.w;
            acc[3][0] += a.w * b.x; acc[3][1] += a.w * b.y; acc[3][2] += a.w * b.z; acc[3][3] += a.w * b.w;
        }
    }
#pragma unroll
    for (int i = 0; i < 4; i++) {
        int m = m0 + ty * 4 + i;
        if (m < M) {
#pragma unroll
            for (int j = 0; j < 4; j++) {
                int n = n0 + tx * 4 + j;
                if (n < N) C[(size_t)m * ldc + n] = acc[i][j];
            }
        }
    }
}

// NN: C[M,N] = A[M,K] @ B[K,N]
__device__ __forceinline__ void sgemm_tile_nn(int M, int N, int K,
                                              const float* __restrict__ A, int lda,
                                              const float* __restrict__ B, int ldb,
                                              float* __restrict__ C, int ldc,
                                              int bx, int by) {
    __shared__ float As[16][68];
    __shared__ float Bs[16][68];
    int n0 = bx * 64, m0 = by * 64;
    int tid = threadIdx.x;
    int tx = tid & 15, ty = tid >> 4;
    float acc[4][4] = {};
    int lm = tid >> 2;
    int lk = (tid & 3) * 4;
    int bk = tid >> 4;
    int bn = (tid & 15) * 4;
    for (int k0 = 0; k0 < K; k0 += 16) {
        float4 av = make_float4(0.f, 0.f, 0.f, 0.f);
        if (m0 + lm < M) av = *(const float4*)&A[(size_t)(m0 + lm) * lda + k0 + lk];
        float4 bv = *(const float4*)&B[(size_t)(k0 + bk) * ldb + n0 + bn];
        __syncthreads();
        As[lk + 0][lm] = av.x; As[lk + 1][lm] = av.y; As[lk + 2][lm] = av.z; As[lk + 3][lm] = av.w;
        *(float4*)&Bs[bk][bn] = bv;
        __syncthreads();
#pragma unroll
        for (int k = 0; k < 16; k++) {
            float4 a = *(const float4*)&As[k][ty * 4];
            float4 b = *(const float4*)&Bs[k][tx * 4];
            acc[0][0] += a.x * b.x; acc[0][1] += a.x * b.y; acc[0][2] += a.x * b.z; acc[0][3] += a.x * b.w;
            acc[1][0] += a.y * b.x; acc[1][1] += a.y * b.y; acc[1][2] += a.y * b.z; acc[1][3] += a.y * b.w;
            acc[2][0] += a.z * b.x; acc[2][1] += a.z * b.y; acc[2][2] += a.z * b.z; acc[2][3] += a.z * b.w;
            acc[3][0] += a.w * b.x; acc[3][1] += a.w * b.y; acc[3][2] += a.w * b.z; acc[3][3] += a.w * b.w;
        }
    }
#pragma unroll
    for (int i = 0; i < 4; i++) {
        int m = m0 + ty * 4 + i;
        if (m < M) {
#pragma unroll
            for (int j = 0; j < 4; j++)
                C[(size_t)m * ldc + n0 + tx * 4 + j] = acc[i][j];
        }
    }
}

__global__ __launch_bounds__(256) void k_sgemm3(const float* __restrict__ q_emb,
                                                const float* __restrict__ q_emb_diff,
                                                const float* __restrict__ w_ih,
                                                const float* __restrict__ matrix,
                                                const float* __restrict__ fc_w) {
    int bid = blockIdx.x;
    if (bid < 408) {
        sgemm_tile_nt(NQC + 1, NG, ND, q_emb, ND, g_wsum, ND, g_WQ, NG,
                      bid % 24, bid / 24);
    } else if (bid < 816) {
        int lb = bid - 408;
        sgemm_tile_nt(NQC + 1, NG, ND, q_emb_diff, ND, w_ih + 256, 512, g_WQD, NG,
                      lb % 24, lb / 24);
    } else {
        int lb = bid - 816;
        sgemm_tile_nn(NQO, NH, NQO, matrix, NQO, fc_w, NH, g_v, NH,
                      lb % 8, lb / 8);
    }
}

// ---------------- xg assembly ----------------
__global__ __launch_bounds__(256) void k_xg(const int* __restrict__ q_data,
                                            const int* __restrict__ qa_data,
                                            const int* __restrict__ pid_data,
                                            const float* __restrict__ diff_parm,
                                            const float* __restrict__ b_ih) {
    int i = blockIdx.x;
    int b = i / NL, l = i % NL;
    int q = q_data[i];
    int a = (qa_data[i] - q) / NQC;
    float pid = diff_parm[pid_data[i]];
    const float* wq  = &g_WQ[(size_t)q * NG];
    const float* wqd = &g_WQD[(size_t)q * NG];
    const float* wa  = &g_WA[(size_t)a * NG];
    const float* wad = &g_WAD[(size_t)a * NG];
    float* dst = &g_xg[(size_t)(l * NB + b) * NG];
    for (int g = threadIdx.x; g < NG; g += 256)
        dst[g] = wq[g] + wa[g] + pid * (wqd[g] + wad[g]) + b_ih[g];
}

// ---------------- persistent GRU: SMEM h + shallow 12-SHFL reduction -------
__global__ __launch_bounds__(256, 1) void k_gru_persist(const float* __restrict__ w_hh,
                                                        const float* __restrict__ b_hh) {
    __shared__ float s_part[48 * PST];       // [row][bi*4 + k] partials, ~13KB
    __shared__ float4 s_h[GBAT * 128];       // 16 batches x 512 floats = 32KB
    int tid  = threadIdx.x;
    int lane = tid & 31, wno = tid >> 5;
    int bx = blockIdx.x;
    int grp = bx & 3;
    int jblk = bx >> 2;
    int j0 = jblk * JBLK;
    int b0 = grp * GBAT;

    unsigned long long wreg[6][8];
#pragma unroll
    for (int r6 = 0; r6 < 6; r6++) {
        int ridx = wno * 6 + r6;
        int gate = ridx >> 4, u = ridx & 15;
        int grow = gate * 512 + j0 + u;
#pragma unroll
        for (int r = 0; r < 4; r++) {
            float4 wv = *(const float4*)&w_hh[(size_t)grow * 512 + r * 128 + lane * 4];
            wreg[r6][2 * r]     = pk2(wv.x, wv.y);
            wreg[r6][2 * r + 1] = pk2(wv.z, wv.w);
        }
    }

    int gu = tid & 15, gbl = tid >> 4;
    int gb = b0 + gbl;
    float bi_r = b_hh[j0 + gu];
    float bi_z = b_hh[512 + j0 + gu];
    float bi_n = b_hh[1024 + j0 + gu];
    float hold = 0.0f;
    int half = lane >> 4;
    bool storer = ((lane & 12) == 0);        // lanes 0-3 and 16-19
    int pk = lane & 3;

    for (int t = 0; t < NL; t++) {
        // prefetch gate inputs for this step (linear addresses)
        const float* xg = &g_xg[((size_t)t * NB + gb) * NG];
        float xr = xg[j0 + gu];
        float xz = xg[512 + j0 + gu];
        float xn = xg[1024 + j0 + gu];

        // cooperative staged load: h[t] for 16 batches (contiguous 32KB), once
        {
            const float4* src = (const float4*)&g_hs[((size_t)t * NB + b0) * NH];
#pragma unroll
            for (int k = 0; k < 8; k++)
                s_h[tid + k * 256] = src[tid + k * 256];
        }
        __syncthreads();

#pragma unroll 2
        for (int bi = 0; bi < GBAT; bi++) {
            unsigned long long cur[8];
#pragma unroll
            for (int r = 0; r < 4; r++) {
                float4 hv = s_h[bi * 128 + r * 32 + lane];
                cur[2 * r]     = pk2(hv.x, hv.y);
                cur[2 * r + 1] = pk2(hv.z, hv.w);
            }
            float acc[6];
#pragma unroll
            for (int r6 = 0; r6 < 6; r6++) {
                unsigned long long a = 0ULL;
#pragma unroll
                for (int r = 0; r < 8; r++) ffma2(a, cur[r], wreg[r6][r]);
                acc[r6] = upk_sum(a);
            }
            // shallow reduction: xor16, pack 6->3, xor8, xor4  (12 SHFL)
#pragma unroll
            for (int r6 = 0; r6 < 6; r6++)
                acc[r6] += __shfl_xor_sync(0xffffffffu, acc[r6], 16);
            float p0 = half ? acc[1] : acc[0];
            float p1 = half ? acc[3] : acc[2];
            float p2 = half ? acc[5] : acc[4];
            p0 += __shfl_xor_sync(0xffffffffu, p0, 8);
            p1 += __shfl_xor_sync(0xffffffffu, p1, 8);
            p2 += __shfl_xor_sync(0xffffffffu, p2, 8);
            p0 += __shfl_xor_sync(0xffffffffu, p0, 4);
            p1 += __shfl_xor_sync(0xffffffffu, p1, 4);
            p2 += __shfl_xor_sync(0xffffffffu, p2, 4);
            // 4 partials per value at lanes 0-3 (half 0) / 16-19 (half 1)
            if (storer) {
                int r = wno * 6 + half;
                s_part[(r + 0) * PST + bi * 4 + pk] = p0;
                s_part[(r + 2) * PST + bi * 4 + pk] = p1;
                s_part[(r + 4) * PST + bi * 4 + pk] = p2;
            }
        }
        __syncthreads();
        // fused gates + h update: finish partial sums here
        {
            float4 v0 = *(const float4*)&s_part[gu * PST + gbl * 4];
            float4 v1 = *(const float4*)&s_part[(16 + gu) * PST + gbl * 4];
            float4 v2 = *(const float4*)&s_part[(32 + gu) * PST + gbl * 4];
            float hr = ((v0.x + v0.y) + (v0.z + v0.w)) + bi_r;
            float hz = ((v1.x + v1.y) + (v1.z + v1.w)) + bi_z;
            float hn = ((v2.x + v2.y) + (v2.z + v2.w)) + bi_n;
            float r = 1.f / (1.f + expf(-(xr + hr)));
            float z = 1.f / (1.f + expf(-(xz + hz)));
            float n = tanhf(xn + r * hn);
            hold = (1.f - z) * n + z * hold;
            g_hs[((size_t)(t + 1) * NB + gb) * NH + j0 + gu] = hold;
        }
        __syncthreads();
        // slot barrier with release/acquire flags (checker block jblk==0)
        if (jblk == 0) {
            if (tid < NBLKG) {
                if (tid > 0)
                    while (ld_acquire(&g_slot[grp][tid]) < t + 1) { }
                __syncwarp(0xffffffffu);
                if (tid == 0) st_release(&g_barf[grp], t + 1);
            }
        } else {
            if (tid == 0) {
                st_release(&g_slot[grp][jblk], t + 1);
                while (ld_acquire(&g_barf[grp]) < t + 1) { }
            }
        }
        __syncthreads();
    }
}

// ---------------- fused tail: mval + counts + dina (per batch) -------------
__global__ __launch_bounds__(256) void k_tail(const int* __restrict__ q_data,
                                              const int* __restrict__ qa_data) {
    __shared__ float s_m[NL], s_qa[NL], s_mc[NL], s_mi[NL], s_nmc[NL], s_aa[NL];
    __shared__ int s_q[NL];
    __shared__ float guess[NQO], slip[NQO];
    int b = blockIdx.x, tid = threadIdx.x;
    int lane = tid & 31, wid = tid >> 5;

    if (tid < NL) {
        int i = b * NL + tid;
        s_q[tid] = q_data[i];
        s_qa[tid] = (float)((qa_data[i] - q_data[i]) / NQC);
    }
    for (int j = tid; j < NQO; j += 256) { guess[j] = 0.f; slip[j] = 0.f; }
    __syncthreads();

    for (int l = wid; l < NL; l += 8) {
        int q = s_q[l] - 1;
        const float* h = &g_hs[(size_t)((l + 1) * NB + b) * NH];
        const float* vr = &g_v[(size_t)q * NH];
        float s = 0.f;
#pragma unroll
        for (int it = 0; it < 4; it++) {
            float4 hv = *(const float4*)&h[it * 128 + lane * 4];
            float4 vv = *(const float4*)&vr[it * 128 + lane * 4];
            s += hv.x * vv.x + hv.y * vv.y + hv.z * vv.z + hv.w * vv.w;
        }
#pragma unroll
        for (int o = 16; o; o >>= 1) s += __shfl_xor_sync(0xffffffffu, s, o);
        if (lane == 0) {
            float got = s + g_c0[q];
            s_m[l] = (got >= 0.4f) ? 1.0f : got;
        }
    }
    __syncthreads();

    if (tid < NL) {
        int qt = s_q[tid];
        float mc = 0.f, mi = 0.f, nmc = 0.f, aa = 1.f;
        for (int k = 0; k < tid; k++) {
            if (s_q[k] == qt) {
                aa += 1.f;
                float m = s_m[k];
                float mast = (m == 1.0f) ? 1.f : 0.f;
                float notm = (m == 0.0f) ? 1.f : 0.f;
                float a1 = s_qa[k], a0 = 1.f - a1;
                mc += a1 * mast; mi += a0 * mast; nmc += a0 * notm;
            }
        }
        s_mc[tid] = mc; s_mi[tid] = mi; s_nmc[tid] = nmc; s_aa[tid] = aa;
    }
    __syncthreads();

    if (tid == 0) {
        for (int t = 0; t < NL; t++) {
            int i = s_q[t] - 1;
            float m = s_m[t], qa = s_qa[t], aa = s_aa[t];
            float g_upd = (m == 1.0f) ? (s_mc[t] / aa)
                          : ((qa == 0.0f) ? (1.f - s_nmc[t] / aa) : (s_nmc[t] / aa));
            bool us = (m == 1.0f) && (qa == 0.0f);
            float ng = us ? guess[i] : g_upd;
            float ns = us ? (s_mi[t] / aa) : slip[i];
            guess[i] = ng; slip[i] = ns;
            float p = (1.f - ns) * (m * ng + (1.f - ns) * (1.f - m));
            g_preds[b * NL + t] = p;
        }
    }
}

// ---------------- final ----------------
__global__ __launch_bounds__(256) void k_final(const float* __restrict__ target,
                                               float* __restrict__ out) {
    int tid = threadIdx.x;
    float mse = 0.f, cnt = 0.f;
    for (int i = tid; i < NBL; i += 256) {
        float p = g_preds[i];
        float lab = target[i];
        float msk = (lab > -0.9f) ? 1.f : 0.f;
        float d = p - lab;
        mse += d * d * msk;
        cnt += msk;
        out[1 + i] = 1.f / (1.f + expf(-p));
    }
    __shared__ float red[256];
    mse = block_reduce256(mse, red);
    cnt = block_reduce256(cnt, red);
    if (tid == 0) {
        out[0] = mse + g_pid2[0] * 1e-5f;
        out[NBL + 1] = cnt;
    }
}

// ---------------- launch ----------------
extern "C" void kernel_launch(void* const* d_in, const int* in_sizes, int n_in,
                              void* d_out, int out_size) {
    const int*   q_data      = (const int*)d_in[0];
    const int*   qa_data     = (const int*)d_in[1];
    const int*   pid_data    = (const int*)d_in[2];
    const float* matrix      = (const float*)d_in[3];
    const float* target      = (const float*)d_in[4];
    const float* q_emb       = (const float*)d_in[5];
    const float* qa_emb      = (const float*)d_in[6];
    const float* q_emb_diff  = (const float*)d_in[7];
    const float* qa_emb_diff = (const float*)d_in[8];
    const float* diff_parm   = (const float*)d_in[9];
    const float* w_ih        = (const float*)d_in[10];
    const float* w_hh        = (const float*)d_in[11];
    const float* b_ih        = (const float*)d_in[12];
    const float* b_hh        = (const float*)d_in[13];
    const float* fc_w        = (const float*)d_in[14];
    const float* fc_b        = (const float*)d_in[15];
    float* out = (float*)d_out;

    k_prep_all<<<2689, 256>>>(w_ih, qa_emb, qa_emb_diff, matrix, fc_b,
                              pid_data, diff_parm);
    k_sgemm3<<<944, 256>>>(q_emb, q_emb_diff, w_ih, matrix, fc_w);
    k_xg<<<NBL, 256>>>(q_data, qa_data, pid_data, diff_parm, b_ih);
    k_gru_persist<<<NBLK, 256>>>(w_hh, b_hh);
    k_tail<<<NB, 256>>>(q_data, qa_data);
    k_final<<<1, 256>>>(target, out);
}

// round 16
// speedup vs baseline: 1.3920x; 1.0075x over previous
#include <cuda_runtime.h>
#include <cuda_bf16.h>
#include <math.h>

#define NB   64
#define NL   200
#define NQC  1024
#define ND   256
#define NH   512
#define NG   1536
#define NQO  1024
#define NBL  (NB*NL)

#define NGRP   4
#define GBAT   16
#define JBLK   16
#define NBLKG  32
#define NBLK   (NGRP*NBLKG)   // 128 persistent blocks
#define PST    68             // s_part row stride

// ---------------- scratch (device globals) ----------------
__device__ float g_WA[2 * NG];
__device__ float g_WAD[2 * NG];
__device__ float g_WQ[(NQC + 1) * NG];
__device__ float g_WQD[(NQC + 1) * NG];
__device__ float g_v[NQO * NH];
__device__ float g_c0[NQO];
__device__ float g_xg[NL * NB * NG];         // [t][b][g] incl b_ih
__device__ float g_hs[(NL + 1) * NB * NH];   // [t][b][j]
__device__ float g_preds[NBL];
__device__ float g_pid2[1];
__device__ int g_slot[NGRP][NBLKG];
__device__ int g_barf[NGRP];

__device__ __forceinline__ float block_reduce256(float v, float* red) {
    int tid = threadIdx.x;
    red[tid] = v;
    __syncthreads();
    for (int s = 128; s > 0; s >>= 1) {
        if (tid < s) red[tid] += red[tid + s];
        __syncthreads();
    }
    float r = red[0];
    __syncthreads();
    return r;
}

// packed f32x2 helpers
__device__ __forceinline__ unsigned long long pk2(float lo, float hi) {
    unsigned long long r;
    asm("mov.b64 %0, {%1, %2};" : "=l"(r) : "f"(lo), "f"(hi));
    return r;
}
__device__ __forceinline__ void ffma2(unsigned long long& d, unsigned long long a,
                                      unsigned long long b) {
    asm("fma.rn.f32x2 %0, %1, %2, %0;" : "+l"(d) : "l"(a), "l"(b));
}
__device__ __forceinline__ float upk_sum(unsigned long long v) {
    float lo, hi;
    asm("mov.b64 {%0, %1}, %2;" : "=f"(lo), "=f"(hi) : "l"(v));
    return lo + hi;
}

// release/acquire flag ops
__device__ __forceinline__ void st_release(int* p, int v) {
    asm volatile("st.release.gpu.global.s32 [%0], %1;" :: "l"(p), "r"(v) : "memory");
}
__device__ __forceinline__ int ld_acquire(int* p) {
    int v;
    asm volatile("ld.acquire.gpu.global.s32 %0, [%1];" : "=r"(v) : "l"(p) : "memory");
    return v;
}

// ---------------- GEMM tiles (shared buffers passed in) ----------------
// NT: C[M,N] = A[M,K] @ B[N,K]^T ; wsum_mode: B row = Brow[k] + Brow[256+k]
__device__ __forceinline__ void sgemm_tile_nt(int M, int N, int K,
                                              const float* __restrict__ A, int lda,
                                              const float* __restrict__ B, int ldb,
                                              float* __restrict__ C, int ldc,
                                              int bx, int by, int wsum_mode,
                                              float (*As)[68], float (*Bs)[68]) {
    int n0 = bx * 64, m0 = by * 64;
    int tid = threadIdx.x;
    int tx = tid & 15, ty = tid >> 4;
    float acc[4][4] = {};
    int lm = tid >> 2;
    int lk = (tid & 3) * 4;
    for (int k0 = 0; k0 < K; k0 += 16) {
        float4 av = make_float4(0.f, 0.f, 0.f, 0.f);
        float4 bv = make_float4(0.f, 0.f, 0.f, 0.f);
        if (m0 + lm < M) av = *(const float4*)&A[(size_t)(m0 + lm) * lda + k0 + lk];
        if (n0 + lm < N) {
            bv = *(const float4*)&B[(size_t)(n0 + lm) * ldb + k0 + lk];
            if (wsum_mode) {
                float4 b2 = *(const float4*)&B[(size_t)(n0 + lm) * ldb + 256 + k0 + lk];
                bv.x += b2.x; bv.y += b2.y; bv.z += b2.z; bv.w += b2.w;
            }
        }
        __syncthreads();
        As[lk + 0][lm] = av.x; As[lk + 1][lm] = av.y; As[lk + 2][lm] = av.z; As[lk + 3][lm] = av.w;
        Bs[lk + 0][lm] = bv.x; Bs[lk + 1][lm] = bv.y; Bs[lk + 2][lm] = bv.z; Bs[lk + 3][lm] = bv.w;
        __syncthreads();
#pragma unroll
        for (int k = 0; k < 16; k++) {
            float4 a = *(const float4*)&As[k][ty * 4];
            float4 b = *(const float4*)&Bs[k][tx * 4];
            acc[0][0] += a.x * b.x; acc[0][1] += a.x * b.y; acc[0][2] += a.x * b.z; acc[0][3] += a.x * b.w;
            acc[1][0] += a.y * b.x; acc[1][1] += a.y * b.y; acc[1][2] += a.y * b.z; acc[1][3] += a.y * b.w;
            acc[2][0] += a.z * b.x; acc[2][1] += a.z * b.y; acc[2][2] += a.z * b.z; acc[2][3] += a.z * b.w;
            acc[3][0] += a.w * b.x; acc[3][1] += a.w * b.y; acc[3][2] += a.w * b.z; acc[3][3] += a.w * b.w;
        }
    }
#pragma unroll
    for (int i = 0; i < 4; i++) {
        int m = m0 + ty * 4 + i;
        if (m < M) {
#pragma unroll
            for (int j = 0; j < 4; j++) {
                int n = n0 + tx * 4 + j;
                if (n < N) C[(size_t)m * ldc + n] = acc[i][j];
            }
        }
    }
}

// NN: C[M,N] = A[M,K] @ B[K,N]
__device__ __forceinline__ void sgemm_tile_nn(int M, int N, int K,
                                              const float* __restrict__ A, int lda,
                                              const float* __restrict__ B, int ldb,
                                              float* __restrict__ C, int ldc,
                                              int bx, int by,
                                              float (*As)[68], float (*Bs)[68]) {
    int n0 = bx * 64, m0 = by * 64;
    int tid = threadIdx.x;
    int tx = tid & 15, ty = tid >> 4;
    float acc[4][4] = {};
    int lm = tid >> 2;
    int lk = (tid & 3) * 4;
    int bk = tid >> 4;
    int bn = (tid & 15) * 4;
    for (int k0 = 0; k0 < K; k0 += 16) {
        float4 av = make_float4(0.f, 0.f, 0.f, 0.f);
        if (m0 + lm < M) av = *(const float4*)&A[(size_t)(m0 + lm) * lda + k0 + lk];
        float4 bv = *(const float4*)&B[(size_t)(k0 + bk) * ldb + n0 + bn];
        __syncthreads();
        As[lk + 0][lm] = av.x; As[lk + 1][lm] = av.y; As[lk + 2][lm] = av.z; As[lk + 3][lm] = av.w;
        *(float4*)&Bs[bk][bn] = bv;
        __syncthreads();
#pragma unroll
        for (int k = 0; k < 16; k++) {
            float4 a = *(const float4*)&As[k][ty * 4];
            float4 b = *(const float4*)&Bs[k][tx * 4];
            acc[0][0] += a.x * b.x; acc[0][1] += a.x * b.y; acc[0][2] += a.x * b.z; acc[0][3] += a.x * b.w;
            acc[1][0] += a.y * b.x; acc[1][1] += a.y * b.y; acc[1][2] += a.y * b.z; acc[1][3] += a.y * b.w;
            acc[2][0] += a.z * b.x; acc[2][1] += a.z * b.y; acc[2][2] += a.z * b.z; acc[2][3] += a.z * b.w;
            acc[3][0] += a.w * b.x; acc[3][1] += a.w * b.y; acc[3][2] += a.w * b.z; acc[3][3] += a.w * b.w;
        }
    }
#pragma unroll
    for (int i = 0; i < 4; i++) {
        int m = m0 + ty * 4 + i;
        if (m < M) {
#pragma unroll
            for (int j = 0; j < 4; j++)
                C[(size_t)m * ldc + n0 + tx * 4 + j] = acc[i][j];
        }
    }
}

// ---------------- single fused prep+GEMM launch (all independent) ----------
// blocks: [0,408) WQ | [408,816) WQD | [816,944) v | [944,2480) WA/WAD
//         [2480,3504) c0 | [3504,3632) zero-h | [3632] pid2
__global__ __launch_bounds__(256) void k_prep_sgemm(const float* __restrict__ w_ih,
                                                    const float* __restrict__ qa_emb,
                                                    const float* __restrict__ qa_emb_diff,
                                                    const float* __restrict__ matrix,
                                                    const float* __restrict__ fc_b,
                                                    const int* __restrict__ pid_data,
                                                    const float* __restrict__ diff_parm,
                                                    const float* __restrict__ q_emb,
                                                    const float* __restrict__ q_emb_diff,
                                                    const float* __restrict__ fc_w) {
    __shared__ float sA[16][68];
    __shared__ float sB[16][68];
    __shared__ float red[256];
    int bid = blockIdx.x, tid = threadIdx.x;
    if (bid < 408) {
        // WQ = q_emb @ (WL+WR)^T, wsum computed on the fly
        sgemm_tile_nt(NQC + 1, NG, ND, q_emb, ND, w_ih, 512, g_WQ, NG,
                      bid % 24, bid / 24, 1, sA, sB);
    } else if (bid < 816) {
        int lb = bid - 408;
        sgemm_tile_nt(NQC + 1, NG, ND, q_emb_diff, ND, w_ih + 256, 512, g_WQD, NG,
                      lb % 24, lb / 24, 0, sA, sB);
    } else if (bid < 944) {
        int lb = bid - 816;
        sgemm_tile_nn(NQO, NH, NQO, matrix, NQO, fc_w, NH, g_v, NH,
                      lb % 8, lb / 8, sA, sB);
    } else if (bid < 2480) {
        int g = bid - 944, d = tid;
        float wl = w_ih[g * 512 + d];
        float r0 = block_reduce256(wl * qa_emb[d], red);
        float r1 = block_reduce256(wl * qa_emb[256 + d], red);
        float r2 = block_reduce256(wl * qa_emb_diff[d], red);
        float r3 = block_reduce256(wl * qa_emb_diff[256 + d], red);
        if (d == 0) {
            g_WA[g] = r0;  g_WA[NG + g] = r1;
            g_WAD[g] = r2; g_WAD[NG + g] = r3;
        }
    } else if (bid < 3504) {
        int k = bid - 2480;
        float s = 0.f;
        for (int q = tid; q < 1024; q += 256) s += matrix[k * 1024 + q] * fc_b[q];
        s = block_reduce256(s, red);
        if (tid == 0) g_c0[k] = s;
    } else if (bid < 3632) {
        int idx = (bid - 3504) * 256 + tid;       // < 64*512
        g_hs[idx] = 0.f;
        if (idx < NGRP) g_barf[idx] = 0;
        if (idx < NGRP * NBLKG) ((int*)g_slot)[idx] = 0;
    } else {
        float s = 0.f;
        for (int i = tid; i < NBL; i += 256) {
            float d = diff_parm[pid_data[i]];
            s += d * d;
        }
        s = block_reduce256(s, red);
        if (tid == 0) g_pid2[0] = s;
    }
}

// ---------------- xg assembly ----------------
__global__ __launch_bounds__(256) void k_xg(const int* __restrict__ q_data,
                                            const int* __restrict__ qa_data,
                                            const int* __restrict__ pid_data,
                                            const float* __restrict__ diff_parm,
                                            const float* __restrict__ b_ih) {
    int i = blockIdx.x;
    int b = i / NL, l = i % NL;
    int q = q_data[i];
    int a = (qa_data[i] - q) / NQC;
    float pid = diff_parm[pid_data[i]];
    const float* wq  = &g_WQ[(size_t)q * NG];
    const float* wqd = &g_WQD[(size_t)q * NG];
    const float* wa  = &g_WA[(size_t)a * NG];
    const float* wad = &g_WAD[(size_t)a * NG];
    float* dst = &g_xg[(size_t)(l * NB + b) * NG];
    for (int g = threadIdx.x; g < NG; g += 256)
        dst[g] = wq[g] + wa[g] + pid * (wqd[g] + wad[g]) + b_ih[g];
}

// ---------------- persistent GRU: identical to R15 (1404.5us) --------------
__global__ __launch_bounds__(256, 1) void k_gru_persist(const float* __restrict__ w_hh,
                                                        const float* __restrict__ b_hh) {
    __shared__ float s_part[48 * PST];
    __shared__ float4 s_h[GBAT * 128];
    int tid  = threadIdx.x;
    int lane = tid & 31, wno = tid >> 5;
    int bx = blockIdx.x;
    int grp = bx & 3;
    int jblk = bx >> 2;
    int j0 = jblk * JBLK;
    int b0 = grp * GBAT;

    unsigned long long wreg[6][8];
#pragma unroll
    for (int r6 = 0; r6 < 6; r6++) {
        int ridx = wno * 6 + r6;
        int gate = ridx >> 4, u = ridx & 15;
        int grow = gate * 512 + j0 + u;
#pragma unroll
        for (int r = 0; r < 4; r++) {
            float4 wv = *(const float4*)&w_hh[(size_t)grow * 512 + r * 128 + lane * 4];
            wreg[r6][2 * r]     = pk2(wv.x, wv.y);
            wreg[r6][2 * r + 1] = pk2(wv.z, wv.w);
        }
    }

    int gu = tid & 15, gbl = tid >> 4;
    int gb = b0 + gbl;
    float bi_r = b_hh[j0 + gu];
    float bi_z = b_hh[512 + j0 + gu];
    float bi_n = b_hh[1024 + j0 + gu];
    float hold = 0.0f;
    int half = lane >> 4;
    bool storer = ((lane & 12) == 0);
    int pk = lane & 3;

    for (int t = 0; t < NL; t++) {
        const float* xg = &g_xg[((size_t)t * NB + gb) * NG];
        float xr = xg[j0 + gu];
        float xz = xg[512 + j0 + gu];
        float xn = xg[1024 + j0 + gu];

        {
            const float4* src = (const float4*)&g_hs[((size_t)t * NB + b0) * NH];
#pragma unroll
            for (int k = 0; k < 8; k++)
                s_h[tid + k * 256] = src[tid + k * 256];
        }
        __syncthreads();

#pragma unroll 2
        for (int bi = 0; bi < GBAT; bi++) {
            unsigned long long cur[8];
#pragma unroll
            for (int r = 0; r < 4; r++) {
                float4 hv = s_h[bi * 128 + r * 32 + lane];
                cur[2 * r]     = pk2(hv.x, hv.y);
                cur[2 * r + 1] = pk2(hv.z, hv.w);
            }
            float acc[6];
#pragma unroll
            for (int r6 = 0; r6 < 6; r6++) {
                unsigned long long a = 0ULL;
#pragma unroll
                for (int r = 0; r < 8; r++) ffma2(a, cur[r], wreg[r6][r]);
                acc[r6] = upk_sum(a);
            }
#pragma unroll
            for (int r6 = 0; r6 < 6; r6++)
                acc[r6] += __shfl_xor_sync(0xffffffffu, acc[r6], 16);
            float p0 = half ? acc[1] : acc[0];
            float p1 = half ? acc[3] : acc[2];
            float p2 = half ? acc[5] : acc[4];
            p0 += __shfl_xor_sync(0xffffffffu, p0, 8);
            p1 += __shfl_xor_sync(0xffffffffu, p1, 8);
            p2 += __shfl_xor_sync(0xffffffffu, p2, 8);
            p0 += __shfl_xor_sync(0xffffffffu, p0, 4);
            p1 += __shfl_xor_sync(0xffffffffu, p1, 4);
            p2 += __shfl_xor_sync(0xffffffffu, p2, 4);
            if (storer) {
                int r = wno * 6 + half;
                s_part[(r + 0) * PST + bi * 4 + pk] = p0;
                s_part[(r + 2) * PST + bi * 4 + pk] = p1;
                s_part[(r + 4) * PST + bi * 4 + pk] = p2;
            }
        }
        __syncthreads();
        {
            float4 v0 = *(const float4*)&s_part[gu * PST + gbl * 4];
            float4 v1 = *(const float4*)&s_part[(16 + gu) * PST + gbl * 4];
            float4 v2 = *(const float4*)&s_part[(32 + gu) * PST + gbl * 4];
            float hr = ((v0.x + v0.y) + (v0.z + v0.w)) + bi_r;
            float hz = ((v1.x + v1.y) + (v1.z + v1.w)) + bi_z;
            float hn = ((v2.x + v2.y) + (v2.z + v2.w)) + bi_n;
            float r = 1.f / (1.f + expf(-(xr + hr)));
            float z = 1.f / (1.f + expf(-(xz + hz)));
            float n = tanhf(xn + r * hn);
            hold = (1.f - z) * n + z * hold;
            g_hs[((size_t)(t + 1) * NB + gb) * NH + j0 + gu] = hold;
        }
        __syncthreads();
        if (jblk == 0) {
            if (tid < NBLKG) {
                if (tid > 0)
                    while (ld_acquire(&g_slot[grp][tid]) < t + 1) { }
                __syncwarp(0xffffffffu);
                if (tid == 0) st_release(&g_barf[grp], t + 1);
            }
        } else {
            if (tid == 0) {
                st_release(&g_slot[grp][jblk], t + 1);
                while (ld_acquire(&g_barf[grp]) < t + 1) { }
            }
        }
        __syncthreads();
    }
}

// ---------------- fused tail: mval + counts + dina (per batch) -------------
__global__ __launch_bounds__(256) void k_tail(const int* __restrict__ q_data,
                                              const int* __restrict__ qa_data) {
    __shared__ float s_m[NL], s_qa[NL], s_mc[NL], s_mi[NL], s_nmc[NL], s_aa[NL];
    __shared__ int s_q[NL];
    __shared__ float guess[NQO], slip[NQO];
    int b = blockIdx.x, tid = threadIdx.x;
    int lane = tid & 31, wid = tid >> 5;

    if (tid < NL) {
        int i = b * NL + tid;
        s_q[tid] = q_data[i];
        s_qa[tid] = (float)((qa_data[i] - q_data[i]) / NQC);
    }
    for (int j = tid; j < NQO; j += 256) { guess[j] = 0.f; slip[j] = 0.f; }
    __syncthreads();

    for (int l = wid; l < NL; l += 8) {
        int q = s_q[l] - 1;
        const float* h = &g_hs[(size_t)((l + 1) * NB + b) * NH];
        const float* vr = &g_v[(size_t)q * NH];
        float s = 0.f;
#pragma unroll
        for (int it = 0; it < 4; it++) {
            float4 hv = *(const float4*)&h[it * 128 + lane * 4];
            float4 vv = *(const float4*)&vr[it * 128 + lane * 4];
            s += hv.x * vv.x + hv.y * vv.y + hv.z * vv.z + hv.w * vv.w;
        }
#pragma unroll
        for (int o = 16; o; o >>= 1) s += __shfl_xor_sync(0xffffffffu, s, o);
        if (lane == 0) {
            float got = s + g_c0[q];
            s_m[l] = (got >= 0.4f) ? 1.0f : got;
        }
    }
    __syncthreads();

    if (tid < NL) {
        int qt = s_q[tid];
        float mc = 0.f, mi = 0.f, nmc = 0.f, aa = 1.f;
        for (int k = 0; k < tid; k++) {
            if (s_q[k] == qt) {
                aa += 1.f;
                float m = s_m[k];
                float mast = (m == 1.0f) ? 1.f : 0.f;
                float notm = (m == 0.0f) ? 1.f : 0.f;
                float a1 = s_qa[k], a0 = 1.f - a1;
                mc += a1 * mast; mi += a0 * mast; nmc += a0 * notm;
            }
        }
        s_mc[tid] = mc; s_mi[tid] = mi; s_nmc[tid] = nmc; s_aa[tid] = aa;
    }
    __syncthreads();

    if (tid == 0) {
        for (int t = 0; t < NL; t++) {
            int i = s_q[t] - 1;
            float m = s_m[t], qa = s_qa[t], aa = s_aa[t];
            float g_upd = (m == 1.0f) ? (s_mc[t] / aa)
                          : ((qa == 0.0f) ? (1.f - s_nmc[t] / aa) : (s_nmc[t] / aa));
            bool us = (m == 1.0f) && (qa == 0.0f);
            float ng = us ? guess[i] : g_upd;
            float ns = us ? (s_mi[t] / aa) : slip[i];
            guess[i] = ng; slip[i] = ns;
            float p = (1.f - ns) * (m * ng + (1.f - ns) * (1.f - m));
            g_preds[b * NL + t] = p;
        }
    }
}

// ---------------- final ----------------
__global__ __launch_bounds__(256) void k_final(const float* __restrict__ target,
                                               float* __restrict__ out) {
    int tid = threadIdx.x;
    float mse = 0.f, cnt = 0.f;
    for (int i = tid; i < NBL; i += 256) {
        float p = g_preds[i];
        float lab = target[i];
        float msk = (lab > -0.9f) ? 1.f : 0.f;
        float d = p - lab;
        mse += d * d * msk;
        cnt += msk;
        out[1 + i] = 1.f / (1.f + expf(-p));
    }
    __shared__ float red[256];
    mse = block_reduce256(mse, red);
    cnt = block_reduce256(cnt, red);
    if (tid == 0) {
        out[0] = mse + g_pid2[0] * 1e-5f;
        out[NBL + 1] = cnt;
    }
}

// ---------------- launch ----------------
extern "C" void kernel_launch(void* const* d_in, const int* in_sizes, int n_in,
                              void* d_out, int out_size) {
    const int*   q_data      = (const int*)d_in[0];
    const int*   qa_data     = (const int*)d_in[1];
    const int*   pid_data    = (const int*)d_in[2];
    const float* matrix      = (const float*)d_in[3];
    const float* target      = (const float*)d_in[4];
    const float* q_emb       = (const float*)d_in[5];
    const float* qa_emb      = (const float*)d_in[6];
    const float* q_emb_diff  = (const float*)d_in[7];
    const float* qa_emb_diff = (const float*)d_in[8];
    const float* diff_parm   = (const float*)d_in[9];
    const float* w_ih        = (const float*)d_in[10];
    const float* w_hh        = (const float*)d_in[11];
    const float* b_ih        = (const float*)d_in[12];
    const float* b_hh        = (const float*)d_in[13];
    const float* fc_w        = (const float*)d_in[14];
    const float* fc_b        = (const float*)d_in[15];
    float* out = (float*)d_out;

    k_prep_sgemm<<<3633, 256>>>(w_ih, qa_emb, qa_emb_diff, matrix, fc_b,
                                pid_data, diff_parm, q_emb, q_emb_diff, fc_w);
    k_xg<<<NBL, 256>>>(q_data, qa_data, pid_data, diff_parm, b_ih);
    k_gru_persist<<<NBLK, 256>>>(w_hh, b_hh);
    k_tail<<<NB, 256>>>(q_data, qa_data);
    k_final<<<1, 256>>>(target, out);
}